// round 1
// baseline (speedup 1.0000x reference)
#include <cuda_runtime.h>
#include <math.h>

// Problem constants
#define SQ    2048          // sequence length
#define HID   1024          // hidden
#define NHEAD 16
#define HD    64            // head dim
#define NB    2             // batch
#define BHN   32            // NB*NHEAD
#define NROWS 4096          // NB*SQ
#define PER   4194304ull    // BHN*SQ*HD  (one of q/k/v)
#define OUT_OFF 4194304ull  // elements of `out` before `weights` in d_out

// attention tiling
#define TQ  16
#define TK  128
#define KVP 65              // kv smem pitch (odd -> conflict-free strided access)
#define SMEM_BYTES ((TQ*SQ + TK*KVP + TQ*HD) * 4)   // 168448

// scratch: q,k,v in [b*h][s][d] layout
__device__ float g_qkv[3ull * PER];

// ---------------------------------------------------------------------------
// Projection GEMM: C[row][col] = sum_k X[row][k] * W[col][k] + bias[col]
// 128x128 tile, BK=8, 256 threads, 8x8 per thread (split 4+4 for bank safety).
// Output scattered into g_qkv[which] with [b,h,s,d] layout.
// ---------------------------------------------------------------------------
__global__ __launch_bounds__(256) void proj_kernel(
    const float* __restrict__ X, const float* __restrict__ W,
    const float* __restrict__ bias, int which)
{
    __shared__ float Xs[8][132];
    __shared__ float Ws[8][132];

    float* outp = g_qkv + (size_t)which * PER;
    int tid = threadIdx.x;
    int tx = tid & 15, ty = tid >> 4;
    int row0 = blockIdx.y * 128, col0 = blockIdx.x * 128;

    int lr = tid >> 1;          // 0..127
    int lk = (tid & 1) * 4;     // 0 or 4
    const float* Xp = X + (size_t)(row0 + lr) * HID + lk;
    const float* Wp = W + (size_t)(col0 + lr) * HID + lk;

    float acc[8][8];
#pragma unroll
    for (int i = 0; i < 8; i++)
#pragma unroll
        for (int j = 0; j < 8; j++) acc[i][j] = 0.f;

    for (int k0 = 0; k0 < HID; k0 += 8) {
        float4 xa = *(const float4*)(Xp + k0);
        float4 wa = *(const float4*)(Wp + k0);
        __syncthreads();
        Xs[lk+0][lr] = xa.x; Xs[lk+1][lr] = xa.y; Xs[lk+2][lr] = xa.z; Xs[lk+3][lr] = xa.w;
        Ws[lk+0][lr] = wa.x; Ws[lk+1][lr] = wa.y; Ws[lk+2][lr] = wa.z; Ws[lk+3][lr] = wa.w;
        __syncthreads();
#pragma unroll
        for (int kk = 0; kk < 8; kk++) {
            float4 a0 = *(const float4*)&Xs[kk][ty*4];
            float4 a1 = *(const float4*)&Xs[kk][64 + ty*4];
            float4 b0 = *(const float4*)&Ws[kk][tx*4];
            float4 b1 = *(const float4*)&Ws[kk][64 + tx*4];
            float a[8] = {a0.x,a0.y,a0.z,a0.w, a1.x,a1.y,a1.z,a1.w};
            float b[8] = {b0.x,b0.y,b0.z,b0.w, b1.x,b1.y,b1.z,b1.w};
#pragma unroll
            for (int i = 0; i < 8; i++)
#pragma unroll
                for (int j = 0; j < 8; j++)
                    acc[i][j] = fmaf(a[i], b[j], acc[i][j]);
        }
    }

#pragma unroll
    for (int i = 0; i < 8; i++) {
        int r = row0 + ((i < 4) ? (ty*4 + i) : (64 + ty*4 + i - 4));
        int bb = r >> 11;           // /SQ
        int ss = r & (SQ - 1);
#pragma unroll
        for (int j = 0; j < 8; j++) {
            int c = col0 + ((j < 4) ? (tx*4 + j) : (64 + tx*4 + j - 4));
            int hh = c >> 6;        // /HD
            int dd = c & (HD - 1);
            outp[(((size_t)(bb * NHEAD + hh)) * SQ + ss) * HD + dd] = acc[i][j] + bias[c];
        }
    }
}

// ---------------------------------------------------------------------------
// Fused attention per (b,h, 16-q-row tile):
//   scores (x 0.25 = 1/sqrt(d)/T) -> smem[16][2048]
//   softmax + threshold (e >= 0.01*sum_e) + L1 renorm -> weights (global + smem)
//   out = weights @ V
// ---------------------------------------------------------------------------
__global__ __launch_bounds__(256) void attn_kernel(
    const unsigned char* __restrict__ mask, float* __restrict__ dout)
{
    extern __shared__ float sm[];
    float* sc = sm;                       // TQ * SQ
    float* kv = sm + TQ * SQ;             // TK * KVP
    float* qs = kv + TK * KVP;            // TQ * HD

    int tid = threadIdx.x;
    int bh  = blockIdx.y;                 // 0..31
    int q0  = blockIdx.x * TQ;
    int b   = bh >> 4;

    const float* qg = g_qkv + ((size_t)bh * SQ + q0) * HD;
    const float* kg = g_qkv + PER        + (size_t)bh * SQ * HD;
    const float* vg = g_qkv + 2ull * PER + (size_t)bh * SQ * HD;

    // Q tile, pre-scaled by 1/sqrt(d)/TEMPERATURE = 0.25
    for (int i = tid; i < TQ * HD; i += 256) qs[i] = qg[i] * 0.25f;

    // ---- Phase A: scores ----
    int cg  = tid & 31;       // column within tile group
    int qg2 = tid >> 5;       // 0..7 -> rows {2*qg2, 2*qg2+1}
    for (int kt = 0; kt < SQ / TK; kt++) {
        __syncthreads();
        for (int i = tid; i < TK * HD; i += 256) {
            int col = i >> 6, dd2 = i & 63;
            kv[col * KVP + dd2] = kg[(size_t)(kt * TK + col) * HD + dd2];
        }
        __syncthreads();
        float acc0[4] = {0,0,0,0}, acc1[4] = {0,0,0,0};
        const float* q0p = qs + (qg2 * 2) * HD;
        const float* q1p = q0p + HD;
#pragma unroll 8
        for (int dd = 0; dd < HD; dd++) {
            float a0 = q0p[dd], a1 = q1p[dd];
#pragma unroll
            for (int j = 0; j < 4; j++) {
                float kk = kv[(cg + 32*j) * KVP + dd];
                acc0[j] = fmaf(a0, kk, acc0[j]);
                acc1[j] = fmaf(a1, kk, acc1[j]);
            }
        }
#pragma unroll
        for (int j = 0; j < 4; j++) {
            sc[(qg2*2 + 0) * SQ + kt*TK + cg + 32*j] = acc0[j];
            sc[(qg2*2 + 1) * SQ + kt*TK + cg + 32*j] = acc1[j];
        }
    }
    __syncthreads();

    // ---- Phase B: softmax + threshold + L1 renorm, write weights ----
    int warp = tid >> 5, lane = tid & 31;
    const unsigned char* mrow = mask + (size_t)b * SQ;
#pragma unroll
    for (int rr = 0; rr < 2; rr++) {
        int r = warp * 2 + rr;
        float* srow = sc + (size_t)r * SQ;

        float m = -3.0e38f;
        for (int i = lane; i < SQ; i += 32)
            if (!mrow[i]) m = fmaxf(m, srow[i]);
#pragma unroll
        for (int o = 16; o; o >>= 1) m = fmaxf(m, __shfl_xor_sync(0xffffffffu, m, o));

        float sum = 0.f;
        for (int i = lane; i < SQ; i += 32) {
            float e = mrow[i] ? 0.f : __expf(srow[i] - m);
            srow[i] = e;
            sum += e;
        }
#pragma unroll
        for (int o = 16; o; o >>= 1) sum += __shfl_xor_sync(0xffffffffu, sum, o);

        float thr = 0.01f * sum;          // w = e/sum < 0.01  <=>  e < thr
        float sum2 = 0.f;
        for (int i = lane; i < SQ; i += 32) {
            float e = srow[i];
            if (e >= thr) sum2 += e;
        }
#pragma unroll
        for (int o = 16; o; o >>= 1) sum2 += __shfl_xor_sync(0xffffffffu, sum2, o);

        // ref: w' = (e*keep/sum) / max(sum2/sum, 1e-12) = e*keep / max(sum2, 1e-12*sum)
        float inv = 1.0f / fmaxf(sum2, 1e-12f * sum);
        if (!(sum > 0.f)) inv = 0.f;      // fully-masked row -> all zeros

        float* gw = dout + OUT_OFF + ((size_t)bh * SQ + (q0 + r)) * SQ;
        for (int i = lane; i < SQ; i += 32) {
            float e = srow[i];
            float w = (e >= thr) ? e * inv : 0.f;
            srow[i] = w;
            gw[i]   = w;
        }
    }
    __syncthreads();

    // ---- Phase C: out = weights @ V ----
    int dx = tid & 15;        // d columns {dx, dx+16, dx+32, dx+48}
    int qr = tid >> 4;        // 0..15
    float oacc[4] = {0,0,0,0};
    for (int vt = 0; vt < SQ / TK; vt++) {
        __syncthreads();
        for (int i = tid; i < TK * HD; i += 256) {
            int col = i >> 6, dd2 = i & 63;
            kv[col * KVP + dd2] = vg[(size_t)(vt * TK + col) * HD + dd2];
        }
        __syncthreads();
        const float* wrow = sc + (size_t)qr * SQ + vt * TK;
#pragma unroll 4
        for (int kk = 0; kk < TK; kk++) {
            float w = wrow[kk];
#pragma unroll
            for (int j = 0; j < 4; j++)
                oacc[j] = fmaf(w, kv[kk * KVP + dx + 16*j], oacc[j]);
        }
    }
    int hh = bh & 15;
    size_t obase = ((size_t)b * SQ + q0 + qr) * HID + (size_t)hh * HD;
#pragma unroll
    for (int j = 0; j < 4; j++) dout[obase + dx + 16*j] = oacc[j];
}

// ---------------------------------------------------------------------------
extern "C" void kernel_launch(void* const* d_in, const int* in_sizes, int n_in,
                              void* d_out, int out_size)
{
    const float* query = (const float*)d_in[0];
    const float* key   = (const float*)d_in[1];
    const float* value = (const float*)d_in[2];
    const unsigned char* mask = (const unsigned char*)d_in[3];
    const float* Wq = (const float*)d_in[4];
    const float* bq = (const float*)d_in[5];
    const float* Wk = (const float*)d_in[6];
    const float* bk = (const float*)d_in[7];
    const float* Wv = (const float*)d_in[8];
    const float* bv = (const float*)d_in[9];
    float* out = (float*)d_out;

    cudaFuncSetAttribute(attn_kernel, cudaFuncAttributeMaxDynamicSharedMemorySize, SMEM_BYTES);

    dim3 g1(HID / 128, NROWS / 128);   // 8 x 32
    proj_kernel<<<g1, 256>>>(query, Wq, bq, 0);
    proj_kernel<<<g1, 256>>>(key,   Wk, bk, 1);
    proj_kernel<<<g1, 256>>>(value, Wv, bv, 2);

    dim3 g2(SQ / TQ, BHN);             // 128 x 32
    attn_kernel<<<g2, 256, SMEM_BYTES>>>(mask, out);
}

// round 7
// speedup vs baseline: 2.1785x; 2.1785x over previous
#include <cuda_runtime.h>
#include <cuda_bf16.h>
#include <cstdint>

#define SQ    2048
#define HID   1024
#define NHEAD 16
#define HD    64
#define BHN   32
#define NROWS 4096
#define OUT_OFF 4194304ull

// 3-term bf16 splits for q,k ([bh][s][d]); 2-term for v ([bh][d][s] transposed)
__device__ __nv_bfloat16 g_qh[4194304], g_qm[4194304], g_ql[4194304];
__device__ __nv_bfloat16 g_kh[4194304], g_km[4194304], g_kl[4194304];
__device__ __nv_bfloat16 g_vh[4194304], g_vl[4194304];

// ---------------- smem layout (bytes) ----------------
#define KP 144                     // K/Q row pitch bytes (72 bf16)
#define VP 272                     // V^T row pitch bytes (136 bf16)
#define WP 528                     // w staging row pitch bytes (132 f32)
#define S_MSK 0
#define S_KH  8192
#define S_KM  (S_KH + 18432)
#define S_KL  (S_KM + 18432)
#define S_VH  (S_KL + 18432)
#define S_VL  (S_VH + 17408)
#define S_SCW (S_VL + 17408)
#define S_TOT (S_SCW + 67584)      // 165888
#define S_QH  S_SCW                // Q staged in SCW region (freed before pass 3 writes)
#define S_QM  (S_SCW + 18432)
#define S_QL  (S_SCW + 36864)

// ---------------- mma helper ----------------
__device__ __forceinline__ void mma16816(float d[4], const uint32_t a[4],
                                         uint32_t b0, uint32_t b1) {
    asm volatile(
        "mma.sync.aligned.m16n8k16.row.col.f32.bf16.bf16.f32 "
        "{%0,%1,%2,%3}, {%4,%5,%6,%7}, {%8,%9}, {%0,%1,%2,%3};"
        : "+f"(d[0]), "+f"(d[1]), "+f"(d[2]), "+f"(d[3])
        : "r"(a[0]), "r"(a[1]), "r"(a[2]), "r"(a[3]), "r"(b0), "r"(b1));
}

__device__ __forceinline__ void split2(float x0, float x1, uint32_t& h, uint32_t& l) {
    __nv_bfloat16 h0 = __float2bfloat16(x0), h1 = __float2bfloat16(x1);
    float r0 = x0 - __bfloat162float(h0), r1 = x1 - __bfloat162float(h1);
    __nv_bfloat16 l0 = __float2bfloat16(r0), l1 = __float2bfloat16(r1);
    h = ((uint32_t)__bfloat16_as_ushort(h1) << 16) | __bfloat16_as_ushort(h0);
    l = ((uint32_t)__bfloat16_as_ushort(l1) << 16) | __bfloat16_as_ushort(l0);
}

// ---------------------------------------------------------------------------
// Projection GEMM (SIMT fp32) -> bf16 split outputs
// ---------------------------------------------------------------------------
__global__ __launch_bounds__(256) void proj_kernel(
    const float* __restrict__ X, const float* __restrict__ W,
    const float* __restrict__ bias, int which, float scl)
{
    __shared__ float Xs[8][132];
    __shared__ float Ws[8][132];

    int tid = threadIdx.x;
    int tx = tid & 15, ty = tid >> 4;
    int row0 = blockIdx.y * 128, col0 = blockIdx.x * 128;

    int lr = tid >> 1;
    int lk = (tid & 1) * 4;
    const float* Xp = X + (size_t)(row0 + lr) * HID + lk;
    const float* Wp = W + (size_t)(col0 + lr) * HID + lk;

    float acc[8][8];
#pragma unroll
    for (int i = 0; i < 8; i++)
#pragma unroll
        for (int j = 0; j < 8; j++) acc[i][j] = 0.f;

    for (int k0 = 0; k0 < HID; k0 += 8) {
        float4 xa = *(const float4*)(Xp + k0);
        float4 wa = *(const float4*)(Wp + k0);
        __syncthreads();
        Xs[lk+0][lr] = xa.x; Xs[lk+1][lr] = xa.y; Xs[lk+2][lr] = xa.z; Xs[lk+3][lr] = xa.w;
        Ws[lk+0][lr] = wa.x; Ws[lk+1][lr] = wa.y; Ws[lk+2][lr] = wa.z; Ws[lk+3][lr] = wa.w;
        __syncthreads();
#pragma unroll
        for (int kk = 0; kk < 8; kk++) {
            float4 a0 = *(const float4*)&Xs[kk][ty*4];
            float4 a1 = *(const float4*)&Xs[kk][64 + ty*4];
            float4 b0 = *(const float4*)&Ws[kk][tx*4];
            float4 b1 = *(const float4*)&Ws[kk][64 + tx*4];
            float a[8] = {a0.x,a0.y,a0.z,a0.w, a1.x,a1.y,a1.z,a1.w};
            float b[8] = {b0.x,b0.y,b0.z,b0.w, b1.x,b1.y,b1.z,b1.w};
#pragma unroll
            for (int i = 0; i < 8; i++)
#pragma unroll
                for (int j = 0; j < 8; j++)
                    acc[i][j] = fmaf(a[i], b[j], acc[i][j]);
        }
    }

#pragma unroll
    for (int i = 0; i < 8; i++) {
        int r = row0 + ((i < 4) ? (ty*4 + i) : (64 + ty*4 + i - 4));
        int bb = r >> 11;
        int ss = r & (SQ - 1);
#pragma unroll
        for (int j = 0; j < 8; j++) {
            int cc = col0 + ((j < 4) ? (tx*4 + j) : (64 + tx*4 + j - 4));
            int hh = cc >> 6;
            int dd = cc & (HD - 1);
            float x = (acc[i][j] + bias[cc]) * scl;
            if (which == 2) {
                size_t idx = ((size_t)(bb * NHEAD + hh) * HD + dd) * SQ + ss;  // transposed
                __nv_bfloat16 h = __float2bfloat16(x);
                __nv_bfloat16 l = __float2bfloat16(x - __bfloat162float(h));
                g_vh[idx] = h; g_vl[idx] = l;
            } else {
                size_t idx = ((size_t)(bb * NHEAD + hh) * SQ + ss) * HD + dd;
                __nv_bfloat16 h = __float2bfloat16(x);
                float r1 = x - __bfloat162float(h);
                __nv_bfloat16 mB = __float2bfloat16(r1);
                float r2 = r1 - __bfloat162float(mB);
                __nv_bfloat16 l = __float2bfloat16(r2);
                if (which == 0) { g_qh[idx] = h; g_qm[idx] = mB; g_ql[idx] = l; }
                else            { g_kh[idx] = h; g_km[idx] = mB; g_kl[idx] = l; }
            }
        }
    }
}

// ---------------------------------------------------------------------------
// Attention: mma.sync bf16 3-term splits, 3-pass flash-style, 128 q-rows/CTA
// ---------------------------------------------------------------------------
__device__ __forceinline__ void ldK(char* sm, int dst, const uint32_t* __restrict__ g) {
    int tid = threadIdx.x;
#pragma unroll
    for (int it = 0; it < 16; it++) {
        int i = it * 256 + tid;
        int r = i >> 5, cc = i & 31;
        *(uint32_t*)(sm + dst + r * KP + cc * 4) = g[r * 32 + cc];
    }
}
__device__ __forceinline__ void ldV(char* sm, int dst, const uint32_t* __restrict__ g) {
    int tid = threadIdx.x;
#pragma unroll
    for (int it = 0; it < 16; it++) {
        int i = it * 256 + tid;
        int r = i >> 6, cc = i & 63;
        *(uint32_t*)(sm + dst + r * VP + cc * 4) = g[r * 1024 + cc];
    }
}

// scores 16 q-rows x 128 kv-cols, 6-combo 3-term splits
__device__ __forceinline__ void qk_tile(const char* sm,
                                        const uint32_t qfh[4][4], const uint32_t qfm[4][4],
                                        const uint32_t qfl[4][4],
                                        int g, int c, float acc[16][4])
{
#pragma unroll
    for (int j = 0; j < 16; j++) {
        acc[j][0] = acc[j][1] = acc[j][2] = acc[j][3] = 0.f;
#pragma unroll
        for (int ks = 0; ks < 4; ks++) {
            int kb = (8 * j + g) * KP + ks * 32 + c * 4;
            uint32_t kh0 = *(const uint32_t*)(sm + S_KH + kb);
            uint32_t kh1 = *(const uint32_t*)(sm + S_KH + kb + 16);
            uint32_t km0 = *(const uint32_t*)(sm + S_KM + kb);
            uint32_t km1 = *(const uint32_t*)(sm + S_KM + kb + 16);
            uint32_t kl0 = *(const uint32_t*)(sm + S_KL + kb);
            uint32_t kl1 = *(const uint32_t*)(sm + S_KL + kb + 16);
            mma16816(acc[j], qfh[ks], kh0, kh1);
            mma16816(acc[j], qfh[ks], km0, km1);
            mma16816(acc[j], qfm[ks], kh0, kh1);
            mma16816(acc[j], qfh[ks], kl0, kl1);
            mma16816(acc[j], qfl[ks], kh0, kh1);
            mma16816(acc[j], qfm[ks], km0, km1);
        }
    }
}

__device__ __forceinline__ void kadd(float& s, float& comp, float e) {
    float y = e - comp;
    float t = s + y;
    comp = (t - s) - y;
    s = t;
}

__global__ __launch_bounds__(256, 1) void attn3_kernel(
    const unsigned char* __restrict__ mask, float* __restrict__ dout)
{
    extern __shared__ char sm[];
    float* smf = (float*)(sm + S_MSK);

    int tid = threadIdx.x, w = tid >> 5, lane = tid & 31;
    int g = lane >> 2, c = lane & 3;
    int bh = blockIdx.y, q0 = blockIdx.x * 128;
    int b = bh >> 4, hh = bh & 15;

    for (int i = tid; i < SQ; i += 256)
        smf[i] = mask[(size_t)b * SQ + i] ? -3.0e38f : 0.0f;

    // stage Q tiles, load fragments
    const uint32_t* qh32 = (const uint32_t*)g_qh + ((size_t)bh * SQ + q0) * 32;
    const uint32_t* qm32 = (const uint32_t*)g_qm + ((size_t)bh * SQ + q0) * 32;
    const uint32_t* ql32 = (const uint32_t*)g_ql + ((size_t)bh * SQ + q0) * 32;
#pragma unroll
    for (int it = 0; it < 16; it++) {
        int i = it * 256 + tid;
        int r = i >> 5, cc = i & 31;
        *(uint32_t*)(sm + S_QH + r * KP + cc * 4) = qh32[r * 32 + cc];
        *(uint32_t*)(sm + S_QM + r * KP + cc * 4) = qm32[r * 32 + cc];
        *(uint32_t*)(sm + S_QL + r * KP + cc * 4) = ql32[r * 32 + cc];
    }
    __syncthreads();

    uint32_t qfh[4][4], qfm[4][4], qfl[4][4];
#pragma unroll
    for (int ks = 0; ks < 4; ks++) {
        int base = (16 * w + g) * KP + ks * 32 + c * 4;
        qfh[ks][0] = *(uint32_t*)(sm + S_QH + base);
        qfh[ks][1] = *(uint32_t*)(sm + S_QH + base + 8 * KP);
        qfh[ks][2] = *(uint32_t*)(sm + S_QH + base + 16);
        qfh[ks][3] = *(uint32_t*)(sm + S_QH + base + 8 * KP + 16);
        qfm[ks][0] = *(uint32_t*)(sm + S_QM + base);
        qfm[ks][1] = *(uint32_t*)(sm + S_QM + base + 8 * KP);
        qfm[ks][2] = *(uint32_t*)(sm + S_QM + base + 16);
        qfm[ks][3] = *(uint32_t*)(sm + S_QM + base + 8 * KP + 16);
        qfl[ks][0] = *(uint32_t*)(sm + S_QL + base);
        qfl[ks][1] = *(uint32_t*)(sm + S_QL + base + 8 * KP);
        qfl[ks][2] = *(uint32_t*)(sm + S_QL + base + 16);
        qfl[ks][3] = *(uint32_t*)(sm + S_QL + base + 8 * KP + 16);
    }

    const uint32_t* kh32 = (const uint32_t*)g_kh + (size_t)bh * SQ * 32;
    const uint32_t* km32 = (const uint32_t*)g_km + (size_t)bh * SQ * 32;
    const uint32_t* kl32 = (const uint32_t*)g_kl + (size_t)bh * SQ * 32;
    const uint32_t* vh32 = (const uint32_t*)g_vh + (size_t)bh * HD * 1024;
    const uint32_t* vl32 = (const uint32_t*)g_vl + (size_t)bh * HD * 1024;

    // ============ PASS 1: per-lane online max + Kahan sum ============
    float m0 = -3.0e38f, m1 = -3.0e38f, s0 = 0.f, s1 = 0.f, c0 = 0.f, c1 = 0.f;
    for (int kt = 0; kt < 16; kt++) {
        __syncthreads();
        ldK(sm, S_KH, kh32 + (size_t)kt * 4096);
        ldK(sm, S_KM, km32 + (size_t)kt * 4096);
        ldK(sm, S_KL, kl32 + (size_t)kt * 4096);
        __syncthreads();
        float acc[16][4];
        qk_tile(sm, qfh, qfm, qfl, g, c, acc);
#pragma unroll
        for (int j = 0; j < 16; j++) {
            float b0 = smf[kt * 128 + 8 * j + 2 * c];
            float b1 = smf[kt * 128 + 8 * j + 2 * c + 1];
            float x0 = acc[j][0] + b0, x1 = acc[j][1] + b1;
            float x2 = acc[j][2] + b0, x3 = acc[j][3] + b1;
            float mx0 = fmaxf(x0, x1), mx1 = fmaxf(x2, x3);
            if (mx0 > m0) { float f = __expf(m0 - mx0); s0 *= f; c0 *= f; m0 = mx0; }
            kadd(s0, c0, __expf(x0 - m0));
            kadd(s0, c0, __expf(x1 - m0));
            if (mx1 > m1) { float f = __expf(m1 - mx1); s1 *= f; c1 *= f; m1 = mx1; }
            kadd(s1, c1, __expf(x2 - m1));
            kadd(s1, c1, __expf(x3 - m1));
        }
    }
    s0 += c0; s1 += c1;
    // reduce (m,s) across the 4 lanes of each row-quad
#pragma unroll
    for (int off = 1; off < 4; off <<= 1) {
        float mo = __shfl_xor_sync(0xffffffffu, m0, off);
        float so = __shfl_xor_sync(0xffffffffu, s0, off);
        float mn = fmaxf(m0, mo);
        s0 = s0 * __expf(m0 - mn) + so * __expf(mo - mn); m0 = mn;
        mo = __shfl_xor_sync(0xffffffffu, m1, off);
        so = __shfl_xor_sync(0xffffffffu, s1, off);
        mn = fmaxf(m1, mo);
        s1 = s1 * __expf(m1 - mn) + so * __expf(mo - mn); m1 = mn;
    }
    float thr0 = 0.01f * s0, thr1 = 0.01f * s1;

    // ============ PASS 2: post-threshold Kahan L1 sum ============
    float s20 = 0.f, s21 = 0.f, c20 = 0.f, c21 = 0.f;
    for (int kt = 0; kt < 16; kt++) {
        __syncthreads();
        ldK(sm, S_KH, kh32 + (size_t)kt * 4096);
        ldK(sm, S_KM, km32 + (size_t)kt * 4096);
        ldK(sm, S_KL, kl32 + (size_t)kt * 4096);
        __syncthreads();
        float acc[16][4];
        qk_tile(sm, qfh, qfm, qfl, g, c, acc);
#pragma unroll
        for (int j = 0; j < 16; j++) {
            float b0 = smf[kt * 128 + 8 * j + 2 * c];
            float b1 = smf[kt * 128 + 8 * j + 2 * c + 1];
            float e0 = __expf(acc[j][0] + b0 - m0);
            float e1 = __expf(acc[j][1] + b1 - m0);
            float e2 = __expf(acc[j][2] + b0 - m1);
            float e3 = __expf(acc[j][3] + b1 - m1);
            if (e0 >= thr0) kadd(s20, c20, e0);
            if (e1 >= thr0) kadd(s20, c20, e1);
            if (e2 >= thr1) kadd(s21, c21, e2);
            if (e3 >= thr1) kadd(s21, c21, e3);
        }
    }
    s20 += c20; s21 += c21;
#pragma unroll
    for (int off = 1; off < 4; off <<= 1) {
        s20 += __shfl_xor_sync(0xffffffffu, s20, off);
        s21 += __shfl_xor_sync(0xffffffffu, s21, off);
    }
    float inv0 = (s0 > 0.f) ? 1.0f / fmaxf(s20, 1e-12f * s0) : 0.f;
    float inv1 = (s1 > 0.f) ? 1.0f / fmaxf(s21, 1e-12f * s1) : 0.f;

    // ============ PASS 3: weights + AV ============
    float oacc[8][4];
#pragma unroll
    for (int jv = 0; jv < 8; jv++)
        oacc[jv][0] = oacc[jv][1] = oacc[jv][2] = oacc[jv][3] = 0.f;

    for (int kt = 0; kt < 16; kt++) {
        __syncthreads();
        ldK(sm, S_KH, kh32 + (size_t)kt * 4096);
        ldK(sm, S_KM, km32 + (size_t)kt * 4096);
        ldK(sm, S_KL, kl32 + (size_t)kt * 4096);
        ldV(sm, S_VH, vh32 + kt * 64);
        ldV(sm, S_VL, vl32 + kt * 64);
        __syncthreads();

        float acc[16][4];
        qk_tile(sm, qfh, qfm, qfl, g, c, acc);
#pragma unroll
        for (int j = 0; j < 16; j++) {
            float b0 = smf[kt * 128 + 8 * j + 2 * c];
            float b1 = smf[kt * 128 + 8 * j + 2 * c + 1];
            float e0 = __expf(acc[j][0] + b0 - m0);
            float e1 = __expf(acc[j][1] + b1 - m0);
            float e2 = __expf(acc[j][2] + b0 - m1);
            float e3 = __expf(acc[j][3] + b1 - m1);
            acc[j][0] = (e0 >= thr0) ? e0 * inv0 : 0.f;
            acc[j][1] = (e1 >= thr0) ? e1 * inv0 : 0.f;
            acc[j][2] = (e2 >= thr1) ? e2 * inv1 : 0.f;
            acc[j][3] = (e3 >= thr1) ? e3 * inv1 : 0.f;
            int ro = (16 * w + g) * WP + (8 * j + 2 * c) * 4;
            *(float2*)(sm + S_SCW + ro) = make_float2(acc[j][0], acc[j][1]);
            *(float2*)(sm + S_SCW + ro + 8 * WP) = make_float2(acc[j][2], acc[j][3]);
        }

        // AV: w fragments straight from registers
#pragma unroll
        for (int kk = 0; kk < 8; kk++) {
            uint32_t ah[4], al[4];
            split2(acc[2*kk][0],   acc[2*kk][1],   ah[0], al[0]);
            split2(acc[2*kk][2],   acc[2*kk][3],   ah[1], al[1]);
            split2(acc[2*kk+1][0], acc[2*kk+1][1], ah[2], al[2]);
            split2(acc[2*kk+1][2], acc[2*kk+1][3], ah[3], al[3]);
#pragma unroll
            for (int jv = 0; jv < 8; jv++) {
                int vb = (8 * jv + g) * VP + kk * 32 + c * 4;
                uint32_t vh0 = *(const uint32_t*)(sm + S_VH + vb);
                uint32_t vh1 = *(const uint32_t*)(sm + S_VH + vb + 16);
                uint32_t vl0 = *(const uint32_t*)(sm + S_VL + vb);
                uint32_t vl1 = *(const uint32_t*)(sm + S_VL + vb + 16);
                mma16816(oacc[jv], ah, vh0, vh1);
                mma16816(oacc[jv], ah, vl0, vl1);
                mma16816(oacc[jv], al, vh0, vh1);
            }
        }
        __syncthreads();

        // coalesced weights write
        float* gw = dout + OUT_OFF + ((size_t)bh * SQ + q0) * SQ + (size_t)kt * 128;
#pragma unroll
        for (int it = 0; it < 16; it++) {
            int i = it * 256 + tid;
            int r = i >> 5, c4 = i & 31;
            float4 v = *(float4*)(sm + S_SCW + r * WP + c4 * 16);
            *(float4*)(gw + (size_t)r * SQ + c4 * 4) = v;
        }
    }

    // final out write
#pragma unroll
    for (int jv = 0; jv < 8; jv++) {
        size_t r0 = ((size_t)b * SQ + q0 + 16 * w + g) * HID + hh * HD + 8 * jv + 2 * c;
        *(float2*)(dout + r0) = make_float2(oacc[jv][0], oacc[jv][1]);
        *(float2*)(dout + r0 + 8 * HID) = make_float2(oacc[jv][2], oacc[jv][3]);
    }
}

// ---------------------------------------------------------------------------
extern "C" void kernel_launch(void* const* d_in, const int* in_sizes, int n_in,
                              void* d_out, int out_size)
{
    const float* query = (const float*)d_in[0];
    const float* key   = (const float*)d_in[1];
    const float* value = (const float*)d_in[2];
    const unsigned char* mask = (const unsigned char*)d_in[3];
    const float* Wq = (const float*)d_in[4];
    const float* bq = (const float*)d_in[5];
    const float* Wk = (const float*)d_in[6];
    const float* bk = (const float*)d_in[7];
    const float* Wv = (const float*)d_in[8];
    const float* bv = (const float*)d_in[9];
    float* out = (float*)d_out;

    cudaFuncSetAttribute(attn3_kernel, cudaFuncAttributeMaxDynamicSharedMemorySize, S_TOT);

    dim3 g1(HID / 128, NROWS / 128);
    proj_kernel<<<g1, 256>>>(query, Wq, bq, 0, 0.25f);   // 1/sqrt(64)/0.5
    proj_kernel<<<g1, 256>>>(key,   Wk, bk, 1, 1.0f);
    proj_kernel<<<g1, 256>>>(value, Wv, bv, 2, 1.0f);

    dim3 g2(SQ / 128, BHN);   // 16 x 32
    attn3_kernel<<<g2, 256, S_TOT>>>(mask, out);
}

// round 8
// speedup vs baseline: 2.4350x; 1.1177x over previous
#include <cuda_runtime.h>
#include <cuda_bf16.h>
#include <cstdint>

#define SQ    2048
#define HID   1024
#define NHEAD 16
#define HD    64
#define BHN   32
#define NROWS 4096
#define OUT_OFF 4194304ull

typedef unsigned long long u64;

// 3-term bf16 splits for q,k ([bh][s][d]); 2-term for v ([bh][d][s] transposed)
__device__ __nv_bfloat16 g_qh[4194304], g_qm[4194304], g_ql[4194304];
__device__ __nv_bfloat16 g_kh[4194304], g_km[4194304], g_kl[4194304];
__device__ __nv_bfloat16 g_vh[4194304], g_vl[4194304];

// ---------------- smem layout (bytes) ----------------
#define KP 144                     // K/Q row pitch bytes (72 bf16)
#define VP 272                     // V^T row pitch bytes (136 bf16)
#define WP 528                     // e/w staging row pitch bytes (132 f32)
#define S_MSK 0
#define S_THR 8192
#define S_INV 8704
#define S_KH  9216
#define S_KM  (S_KH + 18432)
#define S_KL  (S_KM + 18432)
#define S_VH  (S_KL + 18432)
#define S_VL  (S_VH + 17408)
#define S_SCW (S_VL + 17408)
#define S_TOT (S_SCW + 67584)      // 166912
#define S_QH  S_SCW                // Q staged in SCW region (consumed before pass A writes)
#define S_QM  (S_SCW + 18432)
#define S_QL  (S_SCW + 36864)

// ---------------- helpers ----------------
__device__ __forceinline__ void mma16816(float d[4], const uint32_t a[4],
                                         uint32_t b0, uint32_t b1) {
    asm volatile(
        "mma.sync.aligned.m16n8k16.row.col.f32.bf16.bf16.f32 "
        "{%0,%1,%2,%3}, {%4,%5,%6,%7}, {%8,%9}, {%0,%1,%2,%3};"
        : "+f"(d[0]), "+f"(d[1]), "+f"(d[2]), "+f"(d[3])
        : "r"(a[0]), "r"(a[1]), "r"(a[2]), "r"(a[3]), "r"(b0), "r"(b1));
}

__device__ __forceinline__ void split2(float x0, float x1, uint32_t& h, uint32_t& l) {
    __nv_bfloat16 h0 = __float2bfloat16(x0), h1 = __float2bfloat16(x1);
    float r0 = x0 - __bfloat162float(h0), r1 = x1 - __bfloat162float(h1);
    __nv_bfloat16 l0 = __float2bfloat16(r0), l1 = __float2bfloat16(r1);
    h = ((uint32_t)__bfloat16_as_ushort(h1) << 16) | __bfloat16_as_ushort(h0);
    l = ((uint32_t)__bfloat16_as_ushort(l1) << 16) | __bfloat16_as_ushort(l0);
}

__device__ __forceinline__ u64 pack2(float lo, float hi) {
    u64 r; asm("mov.b64 %0, {%1, %2};" : "=l"(r) : "f"(lo), "f"(hi)); return r;
}
__device__ __forceinline__ void unpack2(u64 v, float& lo, float& hi) {
    asm("mov.b64 {%0, %1}, %2;" : "=f"(lo), "=f"(hi) : "l"(v));
}
__device__ __forceinline__ void ffma2(u64& d, u64 a, u64 b) {
    asm("fma.rn.f32x2 %0, %1, %2, %3;" : "=l"(d) : "l"(a), "l"(b), "l"(d));
}

__device__ __forceinline__ void kadd(float& s, float& comp, float e) {
    float y = e - comp;
    float t = s + y;
    comp = (t - s) - y;
    s = t;
}

// ---------------------------------------------------------------------------
// Projection GEMM (SIMT, packed fp32x2 FFMA2) -> bf16 split outputs
// ---------------------------------------------------------------------------
__global__ __launch_bounds__(256) void proj_kernel(
    const float* __restrict__ X, const float* __restrict__ W,
    const float* __restrict__ bias, int which, float scl)
{
    __shared__ float Xs[8][132];
    __shared__ float Ws[8][132];

    int tid = threadIdx.x;
    int tx = tid & 15, ty = tid >> 4;
    int row0 = blockIdx.y * 128, col0 = blockIdx.x * 128;

    int lr = tid >> 1;
    int lk = (tid & 1) * 4;
    const float* Xp = X + (size_t)(row0 + lr) * HID + lk;
    const float* Wp = W + (size_t)(col0 + lr) * HID + lk;

    u64 acc2[8][4];
#pragma unroll
    for (int i = 0; i < 8; i++)
#pragma unroll
        for (int j = 0; j < 4; j++) acc2[i][j] = 0ull;

    for (int k0 = 0; k0 < HID; k0 += 8) {
        float4 xa = *(const float4*)(Xp + k0);
        float4 wa = *(const float4*)(Wp + k0);
        __syncthreads();
        Xs[lk+0][lr] = xa.x; Xs[lk+1][lr] = xa.y; Xs[lk+2][lr] = xa.z; Xs[lk+3][lr] = xa.w;
        Ws[lk+0][lr] = wa.x; Ws[lk+1][lr] = wa.y; Ws[lk+2][lr] = wa.z; Ws[lk+3][lr] = wa.w;
        __syncthreads();
#pragma unroll
        for (int kk = 0; kk < 8; kk++) {
            float4 a0 = *(const float4*)&Xs[kk][ty*4];
            float4 a1 = *(const float4*)&Xs[kk][64 + ty*4];
            float4 b0 = *(const float4*)&Ws[kk][tx*4];
            float4 b1 = *(const float4*)&Ws[kk][64 + tx*4];
            float a[8] = {a0.x,a0.y,a0.z,a0.w, a1.x,a1.y,a1.z,a1.w};
            u64 bp[4];
            bp[0] = pack2(b0.x, b0.y); bp[1] = pack2(b0.z, b0.w);
            bp[2] = pack2(b1.x, b1.y); bp[3] = pack2(b1.z, b1.w);
#pragma unroll
            for (int i = 0; i < 8; i++) {
                u64 aa = pack2(a[i], a[i]);
#pragma unroll
                for (int jp = 0; jp < 4; jp++)
                    ffma2(acc2[i][jp], aa, bp[jp]);
            }
        }
    }

    float acc[8][8];
#pragma unroll
    for (int i = 0; i < 8; i++)
#pragma unroll
        for (int jp = 0; jp < 4; jp++)
            unpack2(acc2[i][jp], acc[i][2*jp], acc[i][2*jp+1]);

#pragma unroll
    for (int i = 0; i < 8; i++) {
        int r = row0 + ((i < 4) ? (ty*4 + i) : (64 + ty*4 + i - 4));
        int bb = r >> 11;
        int ss = r & (SQ - 1);
#pragma unroll
        for (int j = 0; j < 8; j++) {
            int cc = col0 + ((j < 4) ? (tx*4 + j) : (64 + tx*4 + j - 4));
            int hh = cc >> 6;
            int dd = cc & (HD - 1);
            float x = (acc[i][j] + bias[cc]) * scl;
            if (which == 2) {
                size_t idx = ((size_t)(bb * NHEAD + hh) * HD + dd) * SQ + ss;  // transposed
                __nv_bfloat16 h = __float2bfloat16(x);
                __nv_bfloat16 l = __float2bfloat16(x - __bfloat162float(h));
                g_vh[idx] = h; g_vl[idx] = l;
            } else {
                size_t idx = ((size_t)(bb * NHEAD + hh) * SQ + ss) * HD + dd;
                __nv_bfloat16 h = __float2bfloat16(x);
                float r1 = x - __bfloat162float(h);
                __nv_bfloat16 mB = __float2bfloat16(r1);
                float r2 = r1 - __bfloat162float(mB);
                __nv_bfloat16 l = __float2bfloat16(r2);
                if (which == 0) { g_qh[idx] = h; g_qm[idx] = mB; g_ql[idx] = l; }
                else            { g_kh[idx] = h; g_km[idx] = mB; g_kl[idx] = l; }
            }
        }
    }
}

// ---------------------------------------------------------------------------
// Attention: 2-pass (no-max softmax, e cached in the weights buffer) + rescale
// ---------------------------------------------------------------------------
__device__ __forceinline__ void ldK(char* sm, int dst, const uint32_t* __restrict__ g) {
    int tid = threadIdx.x;
#pragma unroll
    for (int it = 0; it < 16; it++) {
        int i = it * 256 + tid;
        int r = i >> 5, cc = i & 31;
        *(uint32_t*)(sm + dst + r * KP + cc * 4) = g[r * 32 + cc];
    }
}
__device__ __forceinline__ void ldV(char* sm, int dst, const uint32_t* __restrict__ g) {
    int tid = threadIdx.x;
#pragma unroll
    for (int it = 0; it < 16; it++) {
        int i = it * 256 + tid;
        int r = i >> 6, cc = i & 63;
        *(uint32_t*)(sm + dst + r * VP + cc * 4) = g[r * 1024 + cc];
    }
}

// scores 16 q-rows x 128 kv-cols, 6-combo 3-term splits
__device__ __forceinline__ void qk_tile(const char* sm,
                                        const uint32_t qfh[4][4], const uint32_t qfm[4][4],
                                        const uint32_t qfl[4][4],
                                        int g, int c, float acc[16][4])
{
#pragma unroll
    for (int j = 0; j < 16; j++) {
        acc[j][0] = acc[j][1] = acc[j][2] = acc[j][3] = 0.f;
#pragma unroll
        for (int ks = 0; ks < 4; ks++) {
            int kb = (8 * j + g) * KP + ks * 32 + c * 4;
            uint32_t kh0 = *(const uint32_t*)(sm + S_KH + kb);
            uint32_t kh1 = *(const uint32_t*)(sm + S_KH + kb + 16);
            uint32_t km0 = *(const uint32_t*)(sm + S_KM + kb);
            uint32_t km1 = *(const uint32_t*)(sm + S_KM + kb + 16);
            uint32_t kl0 = *(const uint32_t*)(sm + S_KL + kb);
            uint32_t kl1 = *(const uint32_t*)(sm + S_KL + kb + 16);
            mma16816(acc[j], qfh[ks], kh0, kh1);
            mma16816(acc[j], qfh[ks], km0, km1);
            mma16816(acc[j], qfm[ks], kh0, kh1);
            mma16816(acc[j], qfh[ks], kl0, kl1);
            mma16816(acc[j], qfl[ks], kh0, kh1);
            mma16816(acc[j], qfm[ks], km0, km1);
        }
    }
}

__global__ __launch_bounds__(256, 1) void attn4_kernel(
    const unsigned char* __restrict__ mask, float* __restrict__ dout)
{
    extern __shared__ char sm[];
    float* smf   = (float*)(sm + S_MSK);
    float* sthr  = (float*)(sm + S_THR);
    float* sinv  = (float*)(sm + S_INV);

    int tid = threadIdx.x, w = tid >> 5, lane = tid & 31;
    int g = lane >> 2, c = lane & 3;
    int bh = blockIdx.y, q0 = blockIdx.x * 128;
    int b = bh >> 4, hh = bh & 15;

    for (int i = tid; i < SQ; i += 256)
        smf[i] = mask[(size_t)b * SQ + i] ? -3.0e38f : 0.0f;

    // stage Q tiles, load fragments
    const uint32_t* qh32 = (const uint32_t*)g_qh + ((size_t)bh * SQ + q0) * 32;
    const uint32_t* qm32 = (const uint32_t*)g_qm + ((size_t)bh * SQ + q0) * 32;
    const uint32_t* ql32 = (const uint32_t*)g_ql + ((size_t)bh * SQ + q0) * 32;
#pragma unroll
    for (int it = 0; it < 16; it++) {
        int i = it * 256 + tid;
        int r = i >> 5, cc = i & 31;
        *(uint32_t*)(sm + S_QH + r * KP + cc * 4) = qh32[r * 32 + cc];
        *(uint32_t*)(sm + S_QM + r * KP + cc * 4) = qm32[r * 32 + cc];
        *(uint32_t*)(sm + S_QL + r * KP + cc * 4) = ql32[r * 32 + cc];
    }
    __syncthreads();

    uint32_t qfh[4][4], qfm[4][4], qfl[4][4];
#pragma unroll
    for (int ks = 0; ks < 4; ks++) {
        int base = (16 * w + g) * KP + ks * 32 + c * 4;
        qfh[ks][0] = *(uint32_t*)(sm + S_QH + base);
        qfh[ks][1] = *(uint32_t*)(sm + S_QH + base + 8 * KP);
        qfh[ks][2] = *(uint32_t*)(sm + S_QH + base + 16);
        qfh[ks][3] = *(uint32_t*)(sm + S_QH + base + 8 * KP + 16);
        qfm[ks][0] = *(uint32_t*)(sm + S_QM + base);
        qfm[ks][1] = *(uint32_t*)(sm + S_QM + base + 8 * KP);
        qfm[ks][2] = *(uint32_t*)(sm + S_QM + base + 16);
        qfm[ks][3] = *(uint32_t*)(sm + S_QM + base + 8 * KP + 16);
        qfl[ks][0] = *(uint32_t*)(sm + S_QL + base);
        qfl[ks][1] = *(uint32_t*)(sm + S_QL + base + 8 * KP);
        qfl[ks][2] = *(uint32_t*)(sm + S_QL + base + 16);
        qfl[ks][3] = *(uint32_t*)(sm + S_QL + base + 8 * KP + 16);
    }

    const uint32_t* kh32 = (const uint32_t*)g_kh + (size_t)bh * SQ * 32;
    const uint32_t* km32 = (const uint32_t*)g_km + (size_t)bh * SQ * 32;
    const uint32_t* kl32 = (const uint32_t*)g_kl + (size_t)bh * SQ * 32;
    const uint32_t* vh32 = (const uint32_t*)g_vh + (size_t)bh * HD * 1024;
    const uint32_t* vl32 = (const uint32_t*)g_vl + (size_t)bh * HD * 1024;

    float* gw = dout + OUT_OFF + ((size_t)bh * SQ + q0) * SQ;

    // ============ PASS A: QK once, e = exp(x) (no max), Kahan sum, e -> gw ============
    float s0 = 0.f, s1 = 0.f, c0 = 0.f, c1 = 0.f;
    for (int kt = 0; kt < 16; kt++) {
        __syncthreads();
        ldK(sm, S_KH, kh32 + (size_t)kt * 4096);
        ldK(sm, S_KM, km32 + (size_t)kt * 4096);
        ldK(sm, S_KL, kl32 + (size_t)kt * 4096);
        __syncthreads();
        float acc[16][4];
        qk_tile(sm, qfh, qfm, qfl, g, c, acc);
#pragma unroll
        for (int j = 0; j < 16; j++) {
            float b0 = smf[kt * 128 + 8 * j + 2 * c];
            float b1 = smf[kt * 128 + 8 * j + 2 * c + 1];
            float e0 = __expf(acc[j][0] + b0);
            float e1 = __expf(acc[j][1] + b1);
            float e2 = __expf(acc[j][2] + b0);
            float e3 = __expf(acc[j][3] + b1);
            kadd(s0, c0, e0); kadd(s0, c0, e1);
            kadd(s1, c1, e2); kadd(s1, c1, e3);
            int ro = (16 * w + g) * WP + (8 * j + 2 * c) * 4;
            *(float2*)(sm + S_SCW + ro) = make_float2(e0, e1);
            *(float2*)(sm + S_SCW + ro + 8 * WP) = make_float2(e2, e3);
        }
        __syncthreads();
        float* gwt = gw + kt * 128;
#pragma unroll
        for (int it = 0; it < 16; it++) {
            int i = it * 256 + tid;
            int r = i >> 5, c4 = i & 31;
            float4 v = *(float4*)(sm + S_SCW + r * WP + c4 * 16);
            *(float4*)(gwt + (size_t)r * SQ + c4 * 4) = v;
        }
    }
    s0 += c0; s1 += c1;
#pragma unroll
    for (int off = 1; off < 4; off <<= 1) {
        s0 += __shfl_xor_sync(0xffffffffu, s0, off);
        s1 += __shfl_xor_sync(0xffffffffu, s1, off);
    }
    float thr0 = 0.01f * s0, thr1 = 0.01f * s1;
    if (c == 0) { sthr[16 * w + g] = thr0; sthr[16 * w + g + 8] = thr1; }

    // ============ PASS B: read e back, threshold, s2, AV (unnormalized) ============
    float oacc[8][4];
#pragma unroll
    for (int jv = 0; jv < 8; jv++)
        oacc[jv][0] = oacc[jv][1] = oacc[jv][2] = oacc[jv][3] = 0.f;
    float s20 = 0.f, s21 = 0.f, c20 = 0.f, c21 = 0.f;

    for (int kt = 0; kt < 16; kt++) {
        __syncthreads();
        ldV(sm, S_VH, vh32 + kt * 64);
        ldV(sm, S_VL, vl32 + kt * 64);
        {
            const float* gwt = gw + kt * 128;
#pragma unroll
            for (int it = 0; it < 16; it++) {
                int i = it * 256 + tid;
                int r = i >> 5, c4 = i & 31;
                float4 v = *(const float4*)(gwt + (size_t)r * SQ + c4 * 4);
                *(float4*)(sm + S_SCW + r * WP + c4 * 16) = v;
            }
        }
        __syncthreads();

        int r0 = 16 * w + g;
#pragma unroll
        for (int kk = 0; kk < 8; kk++) {
            int cb = (16 * kk + 2 * c) * 4;
            float2 w00 = *(float2*)(sm + S_SCW + r0 * WP + cb);
            float2 w08 = *(float2*)(sm + S_SCW + r0 * WP + cb + 32);
            float2 w10 = *(float2*)(sm + S_SCW + (r0 + 8) * WP + cb);
            float2 w18 = *(float2*)(sm + S_SCW + (r0 + 8) * WP + cb + 32);
            w00.x = (w00.x >= thr0) ? w00.x : 0.f;
            w00.y = (w00.y >= thr0) ? w00.y : 0.f;
            w08.x = (w08.x >= thr0) ? w08.x : 0.f;
            w08.y = (w08.y >= thr0) ? w08.y : 0.f;
            w10.x = (w10.x >= thr1) ? w10.x : 0.f;
            w10.y = (w10.y >= thr1) ? w10.y : 0.f;
            w18.x = (w18.x >= thr1) ? w18.x : 0.f;
            w18.y = (w18.y >= thr1) ? w18.y : 0.f;
            kadd(s20, c20, w00.x); kadd(s20, c20, w00.y);
            kadd(s20, c20, w08.x); kadd(s20, c20, w08.y);
            kadd(s21, c21, w10.x); kadd(s21, c21, w10.y);
            kadd(s21, c21, w18.x); kadd(s21, c21, w18.y);

            uint32_t ah[4], al[4];
            split2(w00.x, w00.y, ah[0], al[0]);
            split2(w10.x, w10.y, ah[1], al[1]);
            split2(w08.x, w08.y, ah[2], al[2]);
            split2(w18.x, w18.y, ah[3], al[3]);
#pragma unroll
            for (int jv = 0; jv < 8; jv++) {
                int vb = (8 * jv + g) * VP + kk * 32 + c * 4;
                uint32_t vh0 = *(const uint32_t*)(sm + S_VH + vb);
                uint32_t vh1 = *(const uint32_t*)(sm + S_VH + vb + 16);
                uint32_t vl0 = *(const uint32_t*)(sm + S_VL + vb);
                uint32_t vl1 = *(const uint32_t*)(sm + S_VL + vb + 16);
                mma16816(oacc[jv], ah, vh0, vh1);
                mma16816(oacc[jv], ah, vl0, vl1);
                mma16816(oacc[jv], al, vh0, vh1);
            }
        }
    }
    s20 += c20; s21 += c21;
#pragma unroll
    for (int off = 1; off < 4; off <<= 1) {
        s20 += __shfl_xor_sync(0xffffffffu, s20, off);
        s21 += __shfl_xor_sync(0xffffffffu, s21, off);
    }
    float inv0 = (s0 > 0.f) ? 1.0f / fmaxf(s20, 1e-12f * s0) : 0.f;
    float inv1 = (s1 > 0.f) ? 1.0f / fmaxf(s21, 1e-12f * s1) : 0.f;
    if (c == 0) { sinv[16 * w + g] = inv0; sinv[16 * w + g + 8] = inv1; }

    // scaled out write
#pragma unroll
    for (int jv = 0; jv < 8; jv++) {
        size_t r0o = ((size_t)b * SQ + q0 + 16 * w + g) * HID + hh * HD + 8 * jv + 2 * c;
        *(float2*)(dout + r0o) = make_float2(oacc[jv][0] * inv0, oacc[jv][1] * inv0);
        *(float2*)(dout + r0o + 8 * HID) = make_float2(oacc[jv][2] * inv1, oacc[jv][3] * inv1);
    }
    __syncthreads();

    // ============ PASS C: rescale weights buffer in place ============
    float4* gw4 = (float4*)gw;
#pragma unroll 4
    for (int it = 0; it < 256; it++) {
        int i = it * 256 + tid;
        int r = i >> 9, c4 = i & 511;
        float thr = sthr[r], inv = sinv[r];
        float4 e = gw4[r * 512 + c4];
        e.x = (e.x >= thr) ? e.x * inv : 0.f;
        e.y = (e.y >= thr) ? e.y * inv : 0.f;
        e.z = (e.z >= thr) ? e.z * inv : 0.f;
        e.w = (e.w >= thr) ? e.w * inv : 0.f;
        gw4[r * 512 + c4] = e;
    }
}

// ---------------------------------------------------------------------------
extern "C" void kernel_launch(void* const* d_in, const int* in_sizes, int n_in,
                              void* d_out, int out_size)
{
    const float* query = (const float*)d_in[0];
    const float* key   = (const float*)d_in[1];
    const float* value = (const float*)d_in[2];
    const unsigned char* mask = (const unsigned char*)d_in[3];
    const float* Wq = (const float*)d_in[4];
    const float* bq = (const float*)d_in[5];
    const float* Wk = (const float*)d_in[6];
    const float* bk = (const float*)d_in[7];
    const float* Wv = (const float*)d_in[8];
    const float* bv = (const float*)d_in[9];
    float* out = (float*)d_out;

    cudaFuncSetAttribute(attn4_kernel, cudaFuncAttributeMaxDynamicSharedMemorySize, S_TOT);

    dim3 g1(HID / 128, NROWS / 128);
    proj_kernel<<<g1, 256>>>(query, Wq, bq, 0, 0.25f);   // 1/sqrt(64)/0.5
    proj_kernel<<<g1, 256>>>(key,   Wk, bk, 1, 1.0f);
    proj_kernel<<<g1, 256>>>(value, Wv, bv, 2, 1.0f);

    dim3 g2(SQ / 128, BHN);   // 16 x 32
    attn4_kernel<<<g2, 256, S_TOT>>>(mask, out);
}